// round 3
// baseline (speedup 1.0000x reference)
#include <cuda_runtime.h>
#include <math.h>

#define B_  8
#define T_  4096
#define D_  1024
#define D4_ 256
#define S_  16
#define H_  256
#define W_  241
#define NP_ 256

__constant__ int c_alias[64] = {
  -1,-1,-1,-1,-1,-1,-1,-1,-1,-1,   // 0-9
  -1,11,-1,11,-1,-1,11,-1,-1,-1,   // 10-19
  -1,21,21,21,-1,-1,-1,-1,-1,-1,   // 20-29
  -1,31,31,31,-1,-1,-1,-1,-1,-1,   // 30-39
  -1,41,41,41,41,-1,-1,-1,-1,-1,   // 40-49
  -1,51,51,51,-1,-1,-1,-1,-1,-1,   // 50-59
  -1,-1,-1,-1                      // 60-63
};

// Block reductions (blockDim = 256, 8 warps)
__device__ __forceinline__ float bsum(float v, volatile float* sred) {
#pragma unroll
  for (int o = 16; o; o >>= 1) v += __shfl_xor_sync(0xffffffffu, v, o);
  __syncthreads();
  if ((threadIdx.x & 31) == 0) sred[threadIdx.x >> 5] = v;
  __syncthreads();
  float t = 0.f;
#pragma unroll
  for (int i = 0; i < 8; i++) t += sred[i];
  return t;
}
__device__ __forceinline__ float bmax(float v, volatile float* sred) {
#pragma unroll
  for (int o = 16; o; o >>= 1) v = fmaxf(v, __shfl_xor_sync(0xffffffffu, v, o));
  __syncthreads();
  if ((threadIdx.x & 31) == 0) sred[threadIdx.x >> 5] = v;
  __syncthreads();
  float t = sred[0];
#pragma unroll
  for (int i = 1; i < 8; i++) t = fmaxf(t, sred[i]);
  return t;
}

// ---------------------------------------------------------------------------
// Fused kernel: one CTA per (b, a) pair. 256 threads = 8 warps.
// Phase 1: stream future = hidden[b, start:start+256, :1024] (1 MB) —
//   warp w owns rows {w, w+8, ...} (32 rows), LDG.128, register column
//   accumulators, per-row sq-norm via warp shuffle.
// Phase 2: cross-warp column combine in smem -> cosine sim (no global
//   scratch round-trip).
// Phase 3: token/window logic (vocab=64 -> uint64 bitmask tricks).
// ---------------------------------------------------------------------------
__global__ void __launch_bounds__(256) k_fused(
    const float* __restrict__ hidden, const float* __restrict__ anchor,
    const int* __restrict__ ids, const int* __restrict__ anchor_end,
    float* __restrict__ out) {
  __shared__ float4 sanchor[D4_];        // 4 KB
  __shared__ float4 swarp[8][D4_];       // 32 KB
  __shared__ float sShiftW[8];
  __shared__ float sred[8];
  __shared__ int ftok[H_];
  __shared__ int sspan[S_];
  __shared__ int salias[64];
  __shared__ int s_root, s_hasT;
  __shared__ float s_invden;
  __shared__ unsigned long long s_dmask, s_cmask;

  const int p = blockIdx.x;
  const int b = p >> 5;
  const int tid = threadIdx.x;
  const int warp = tid >> 5, lane = tid & 31;
  const int ae = anchor_end[p];
  const int start = ae + 1;

  // Token loads (cheap, overlap with anchor load)
  ftok[tid] = ids[b * T_ + start + tid];
  if (tid < S_) sspan[tid] = ids[b * T_ + ae - (S_ - 1) + tid];
  if (tid < 64) salias[tid] = c_alias[tid];

  const float4* anchor4 = (const float4*)(anchor + (size_t)p * D_);
  for (int i = tid; i < D4_; i += 256) sanchor[i] = __ldg(anchor4 + i);
  __syncthreads();

  // ---- Phase 1: stream 256 rows x 1024 cols ----
  float4 colacc[8];
#pragma unroll
  for (int j = 0; j < 8; j++) colacc[j] = make_float4(0.f, 0.f, 0.f, 0.f);
  float shiftsum = 0.f;

  const float4* base4 = (const float4*)(hidden + ((size_t)b * T_ + start) * D_);
#pragma unroll 4
  for (int r = 0; r < 32; r++) {
    const float4* row4 = base4 + (size_t)(warp + 8 * r) * D4_;
    float ssq = 0.f;
#pragma unroll
    for (int j = 0; j < 8; j++) {
      float4 x = __ldg(row4 + lane + 32 * j);
      float4 a = sanchor[lane + 32 * j];
      colacc[j].x += x.x; colacc[j].y += x.y;
      colacc[j].z += x.z; colacc[j].w += x.w;
      float d0 = x.x - a.x, d1 = x.y - a.y, d2 = x.z - a.z, d3 = x.w - a.w;
      ssq += d0 * d0 + d1 * d1 + d2 * d2 + d3 * d3;
    }
#pragma unroll
    for (int o = 16; o; o >>= 1) ssq += __shfl_xor_sync(0xffffffffu, ssq, o);
    shiftsum += sqrtf(ssq);
  }
#pragma unroll
  for (int j = 0; j < 8; j++) swarp[warp][lane + 32 * j] = colacc[j];
  if (lane == 0) sShiftW[warp] = shiftsum;
  __syncthreads();

  // ---- Phase 2: column combine + cosine sim (thread tid owns float4 col tid)
  float dot, nm, na;
  {
    float4 s = swarp[0][tid];
#pragma unroll
    for (int w = 1; w < 8; w++) {
      float4 t = swarp[w][tid];
      s.x += t.x; s.y += t.y; s.z += t.z; s.w += t.w;
    }
    const float invH = 1.f / H_;
    float4 m = make_float4(s.x * invH, s.y * invH, s.z * invH, s.w * invH);
    float4 a = sanchor[tid];
    dot = m.x * a.x + m.y * a.y + m.z * a.z + m.w * a.w;
    nm  = m.x * m.x + m.y * m.y + m.z * m.z + m.w * m.w;
    na  = a.x * a.x + a.y * a.y + a.z * a.z + a.w * a.w;
  }
  dot = bsum(dot, sred);
  nm = bsum(nm, sred);
  na = bsum(na, sred);
  const float eps = 1e-8f;
  float sim = dot / (fmaxf(sqrtf(na), eps) * fmaxf(sqrtf(nm), eps));
  float hidden_c = fmaxf(0.f, (1.f - sim) * 0.5f);

  // token_c
  int atok = sspan[S_ - 1];
  float tcnt = (ftok[tid] == atok) ? 1.f : 0.f;
  tcnt = bsum(tcnt, sred);
  float token_c = 1.f - tcnt * (1.f / H_);

  // ---- Phase 3: span analysis (single thread, trivially cheap) ----
  if (tid == 0) {
    unsigned long long dm = 0ull;
    int denom = 0;
    for (int s = 0; s < S_; s++) {
      unsigned long long bit = 1ull << sspan[s];
      if (!(dm & bit)) { dm |= bit; denom++; }
    }
    int counts[S_], maxc = 0;
    for (int s = 0; s < S_; s++) {
      int c = 0;
      for (int s2 = 0; s2 < S_; s2++) c += (sspan[s] == sspan[s2]);
      counts[s] = c;
      maxc = max(maxc, c);
    }
    int mode = 64;
    for (int s = 0; s < S_; s++)
      if (counts[s] == maxc) mode = min(mode, sspan[s]);
    int root = -1;
    for (int s = 0; s < S_; s++) {
      int al = salias[sspan[s]];
      if (al >= 0) { root = al; break; }
    }
    if (root < 0) root = mode;
    unsigned long long cm = 0ull;
    switch (root) {
      case 11: cm = (1ull<<11)|(1ull<<13)|(1ull<<16); break;
      case 21: cm = (1ull<<14)|(1ull<<15)|(1ull<<21)|(1ull<<22)|(1ull<<23); break;
      case 31: cm = (1ull<<15)|(1ull<<31)|(1ull<<32)|(1ull<<33); break;
      case 41: cm = (1ull<<41)|(1ull<<42)|(1ull<<43)|(1ull<<44); break;
      case 51: cm = (1ull<<15)|(1ull<<51)|(1ull<<52)|(1ull<<53); break;
      default: break;
    }
    s_root = root;
    s_cmask = cm;
    s_hasT = (cm != 0ull) ? 1 : 0;
    s_dmask = dm;
    s_invden = 1.f / (float)denom;
  }
  __syncthreads();

  const int root = s_root;
  const unsigned long long cmask = s_cmask, dmask = s_dmask;
  const int hasT = s_hasT;
  const float invden = s_invden;

  // ---- Window scoring: one thread per window (W=241) ----
  float sims = 0.f, rp = 0.f, regime = 0.f, hit = 0.f;
  float simmax = -1e30f;
  if (tid < W_) {
    float ex = 0.f, pos = 0.f, ac = 0.f, hd = 0.f;
    unsigned long long wm = 0ull;
#pragma unroll
    for (int s = 0; s < S_; s++) {
      int tok = ftok[tid + s];
      wm |= 1ull << tok;
      float eq = (tok == sspan[s]) ? 1.f : 0.f;
      ex += eq;
      pos += eq * (1.0f - 0.04f * (float)s);
      rp += (tok == root) ? 1.f : 0.f;
      ac += (salias[tok] == root) ? 1.f : 0.f;
      hd += (float)((cmask >> tok) & 1ull);
    }
    ex *= (1.f / S_);
    pos *= (1.f / 11.2f);
    rp *= (1.f / S_);
    ac *= (1.f / S_);
    hd *= (1.f / S_);
    float ov = (float)__popcll(wm & dmask) * invden;
    regime = hasT ? (0.55f * hd + 0.2f * ov + 0.15f * ac + 0.1f * rp)
                  : (0.45f * ex + 0.3f * ov + 0.1f * ac + 0.15f * rp);
    sims = 0.25f * ex + 0.15f * ov + 0.35f * pos + 0.25f * regime;
    simmax = sims;
    hit = (sims >= 0.6f) ? 1.f : 0.f;
  }
  float sum_sims = bsum(sims, sred);
  float sum_rp   = bsum(rp, sred);
  float sum_reg  = bsum(regime, sred);
  float sum_hit  = bsum(hit, sred);
  float best     = bmax(simmax, sred);

  if (tid == 0) {
    const float invW = 1.f / (float)W_;
    float msims = sum_sims * invW;
    float mrp = sum_rp * invW;
    float mrc = sum_reg * invW;
    float dmass = sum_hit * invW;
    float dcoh = 0.6f * msims + 0.25f * mrp + 0.15f * mrc;
    float pattern_c = 1.f - (0.6f * best + 0.2f * mrp + 0.2f * mrc);
    float contr = 0.2f * hidden_c + 0.2f * token_c + 0.6f * pattern_c;
    contr = fminf(fmaxf(contr, 0.f), 1.f);
    float sh = 0.f;
#pragma unroll
    for (int w = 0; w < 8; w++) sh += sShiftW[w];
    sh *= (1.f / H_);
    out[0 * NP_ + p] = contr;
    out[1 * NP_ + p] = sh;
    out[2 * NP_ + p] = sim;
    out[3 * NP_ + p] = hidden_c;
    out[4 * NP_ + p] = token_c;
    out[5 * NP_ + p] = pattern_c;
    out[6 * NP_ + p] = dmass;
    out[7 * NP_ + p] = dcoh;
  }
}

extern "C" void kernel_launch(void* const* d_in, const int* in_sizes, int n_in,
                              void* d_out, int out_size) {
  const float* hidden = (const float*)d_in[0];
  const float* anchor = (const float*)d_in[1];
  const int* ids = (const int*)d_in[2];
  const int* ae = (const int*)d_in[3];
  float* out = (float*)d_out;
  k_fused<<<NP_, 256>>>(hidden, anchor, ids, ae, out);
}

// round 6
// speedup vs baseline: 1.5311x; 1.5311x over previous
#include <cuda_runtime.h>
#include <math.h>

#define B_  8
#define T_  4096
#define D_  1024
#define D4_ 256
#define S_  16
#define H_  256
#define W_  241
#define NP_ 256
#define RB_ 8

// Cross-CTA scratch: per-(pair,rowblock) column partial sums + shift partials.
__device__ float g_partial[NP_][RB_][D_];
__device__ float g_shiftp[NP_][RB_];
__device__ unsigned int g_count[NP_];   // zero-init; finalizer resets -> replay-safe

__constant__ int c_alias[64] = {
  -1,-1,-1,-1,-1,-1,-1,-1,-1,-1,   // 0-9
  -1,11,-1,11,-1,-1,11,-1,-1,-1,   // 10-19
  -1,21,21,21,-1,-1,-1,-1,-1,-1,   // 20-29
  -1,31,31,31,-1,-1,-1,-1,-1,-1,   // 30-39
  -1,41,41,41,41,-1,-1,-1,-1,-1,   // 40-49
  -1,51,51,51,-1,-1,-1,-1,-1,-1,   // 50-59
  -1,-1,-1,-1                      // 60-63
};

__device__ __forceinline__ float bsum(float v, volatile float* sred) {
#pragma unroll
  for (int o = 16; o; o >>= 1) v += __shfl_xor_sync(0xffffffffu, v, o);
  __syncthreads();
  if ((threadIdx.x & 31) == 0) sred[threadIdx.x >> 5] = v;
  __syncthreads();
  float t = 0.f;
#pragma unroll
  for (int i = 0; i < 8; i++) t += sred[i];
  return t;
}
__device__ __forceinline__ float bmax(float v, volatile float* sred) {
#pragma unroll
  for (int o = 16; o; o >>= 1) v = fmaxf(v, __shfl_xor_sync(0xffffffffu, v, o));
  __syncthreads();
  if ((threadIdx.x & 31) == 0) sred[threadIdx.x >> 5] = v;
  __syncthreads();
  float t = sred[0];
#pragma unroll
  for (int i = 1; i < 8; i++) t = fmaxf(t, sred[i]);
  return t;
}

// ---------------------------------------------------------------------------
// Single kernel, grid (256 pairs, 8 rowblocks), 256 threads.
// Streaming phase identical in shape to the round-2 winner (each warp owns 4
// rows of 32 float4s, LDG.128, ssq reductions deferred past the load loop).
// The 8th CTA to finish a pair runs the finalize inline (fence+atomic
// protocol), overlapping finalize latency with other pairs' streaming.
// ---------------------------------------------------------------------------
__global__ void __launch_bounds__(256, 4) k_all(
    const float* __restrict__ hidden, const float* __restrict__ anchor,
    const int* __restrict__ ids, const int* __restrict__ anchor_end,
    float* __restrict__ out) {
  __shared__ float4 sanchor[D4_];        // 4 KB
  __shared__ float4 swarp[8][D4_];       // 32 KB
  __shared__ float sShiftW[8];
  __shared__ float sred[8];
  __shared__ int ftok[H_];
  __shared__ int sspan[S_];
  __shared__ int salias[64];
  __shared__ int s_last;
  __shared__ int s_root, s_hasT;
  __shared__ float s_invden;
  __shared__ unsigned long long s_dmask, s_cmask;

  const int p = blockIdx.x, rb = blockIdx.y;
  const int tid = threadIdx.x;
  const int warp = tid >> 5, lane = tid & 31;
  const int b = p >> 5;
  const int ae = anchor_end[p];
  const int start = ae + 1;

  const float4* anchor4 = (const float4*)(anchor + (size_t)p * D_);
  for (int i = tid; i < D4_; i += 256) sanchor[i] = __ldg(anchor4 + i);
  __syncthreads();

  // ---- Streaming: 32 rows (4 per warp) x 1024 cols ----
  float4 colacc[8];
#pragma unroll
  for (int j = 0; j < 8; j++) colacc[j] = make_float4(0.f, 0.f, 0.f, 0.f);
  float ssqr[4];

  const float4* base4 =
      (const float4*)(hidden + ((size_t)b * T_ + start + rb * 32) * D_);
#pragma unroll
  for (int r = 0; r < 4; r++) {
    const float4* row4 = base4 + (size_t)(warp + 8 * r) * D4_;
    float ssq = 0.f;
#pragma unroll
    for (int j = 0; j < 8; j++) {
      float4 x = __ldg(row4 + lane + 32 * j);
      float4 a = sanchor[lane + 32 * j];
      colacc[j].x += x.x; colacc[j].y += x.y;
      colacc[j].z += x.z; colacc[j].w += x.w;
      float d0 = x.x - a.x, d1 = x.y - a.y, d2 = x.z - a.z, d3 = x.w - a.w;
      ssq += d0 * d0 + d1 * d1 + d2 * d2 + d3 * d3;
    }
    ssqr[r] = ssq;   // defer warp reduction: keep loads flowing
  }
  float shiftsum = 0.f;
#pragma unroll
  for (int r = 0; r < 4; r++) {
    float v = ssqr[r];
#pragma unroll
    for (int o = 16; o; o >>= 1) v += __shfl_xor_sync(0xffffffffu, v, o);
    shiftsum += sqrtf(v);
  }

#pragma unroll
  for (int j = 0; j < 8; j++) swarp[warp][lane + 32 * j] = colacc[j];
  if (lane == 0) sShiftW[warp] = shiftsum;
  __syncthreads();

  // Cross-warp combine -> global partials (thread tid owns float4 col tid)
  {
    float4 s = swarp[0][tid];
#pragma unroll
    for (int w = 1; w < 8; w++) {
      float4 t = swarp[w][tid];
      s.x += t.x; s.y += t.y; s.z += t.z; s.w += t.w;
    }
    ((float4*)g_partial[p][rb])[tid] = s;
  }
  if (tid == 0) {
    float sh = 0.f;
#pragma unroll
    for (int w = 0; w < 8; w++) sh += sShiftW[w];
    g_shiftp[p][rb] = sh;
  }

  // ---- Arrival protocol: last CTA of the pair finalizes ----
  __threadfence();
  __syncthreads();
  if (tid == 0) {
    unsigned int old = atomicAdd(&g_count[p], 1u);
    s_last = (old == RB_ - 1) ? 1 : 0;
    if (s_last) g_count[p] = 0;   // reset for next graph replay
  }
  __syncthreads();
  if (!s_last) return;
  __threadfence();   // acquire side: order partial reads after the atomic

  // ================== FINALIZE (one CTA per pair) ==================
  ftok[tid] = ids[b * T_ + start + tid];
  if (tid < S_) sspan[tid] = ids[b * T_ + ae - (S_ - 1) + tid];
  if (tid < 64) salias[tid] = c_alias[tid];

  // cosine sim from the 8 rowblock partials (L2-hot)
  float dot, nm, na;
  {
    float4 s = make_float4(0.f, 0.f, 0.f, 0.f);
#pragma unroll
    for (int r = 0; r < RB_; r++) {
      float4 t = ((const float4*)g_partial[p][r])[tid];
      s.x += t.x; s.y += t.y; s.z += t.z; s.w += t.w;
    }
    const float invH = 1.f / H_;
    float4 m = make_float4(s.x * invH, s.y * invH, s.z * invH, s.w * invH);
    float4 a = sanchor[tid];
    dot = m.x * a.x + m.y * a.y + m.z * a.z + m.w * a.w;
    nm  = m.x * m.x + m.y * m.y + m.z * m.z + m.w * m.w;
    na  = a.x * a.x + a.y * a.y + a.z * a.z + a.w * a.w;
  }
  dot = bsum(dot, sred);
  nm = bsum(nm, sred);
  na = bsum(na, sred);
  const float eps = 1e-8f;
  float sim = dot / (fmaxf(sqrtf(na), eps) * fmaxf(sqrtf(nm), eps));
  float hidden_c = fmaxf(0.f, (1.f - sim) * 0.5f);

  int atok = sspan[S_ - 1];
  float tcnt = (ftok[tid] == atok) ? 1.f : 0.f;
  tcnt = bsum(tcnt, sred);
  float token_c = 1.f - tcnt * (1.f / H_);

  if (tid == 0) {
    unsigned long long dm = 0ull;
    int denom = 0;
    for (int s = 0; s < S_; s++) {
      unsigned long long bit = 1ull << sspan[s];
      if (!(dm & bit)) { dm |= bit; denom++; }
    }
    int counts[S_], maxc = 0;
    for (int s = 0; s < S_; s++) {
      int c = 0;
      for (int s2 = 0; s2 < S_; s2++) c += (sspan[s] == sspan[s2]);
      counts[s] = c;
      maxc = max(maxc, c);
    }
    int mode = 64;
    for (int s = 0; s < S_; s++)
      if (counts[s] == maxc) mode = min(mode, sspan[s]);
    int root = -1;
    for (int s = 0; s < S_; s++) {
      int al = salias[sspan[s]];
      if (al >= 0) { root = al; break; }
    }
    if (root < 0) root = mode;
    unsigned long long cm = 0ull;
    switch (root) {
      case 11: cm = (1ull<<11)|(1ull<<13)|(1ull<<16); break;
      case 21: cm = (1ull<<14)|(1ull<<15)|(1ull<<21)|(1ull<<22)|(1ull<<23); break;
      case 31: cm = (1ull<<15)|(1ull<<31)|(1ull<<32)|(1ull<<33); break;
      case 41: cm = (1ull<<41)|(1ull<<42)|(1ull<<43)|(1ull<<44); break;
      case 51: cm = (1ull<<15)|(1ull<<51)|(1ull<<52)|(1ull<<53); break;
      default: break;
    }
    s_root = root;
    s_cmask = cm;
    s_hasT = (cm != 0ull) ? 1 : 0;
    s_dmask = dm;
    s_invden = 1.f / (float)denom;
  }
  __syncthreads();

  const int root = s_root;
  const unsigned long long cmask = s_cmask, dmask = s_dmask;
  const int hasT = s_hasT;
  const float invden = s_invden;

  float sims = 0.f, rp = 0.f, regime = 0.f, hit = 0.f;
  float simmax = -1e30f;
  if (tid < W_) {
    float ex = 0.f, pos = 0.f, ac = 0.f, hd = 0.f;
    unsigned long long wm = 0ull;
#pragma unroll
    for (int s = 0; s < S_; s++) {
      int tok = ftok[tid + s];
      wm |= 1ull << tok;
      float eq = (tok == sspan[s]) ? 1.f : 0.f;
      ex += eq;
      pos += eq * (1.0f - 0.04f * (float)s);
      rp += (tok == root) ? 1.f : 0.f;
      ac += (salias[tok] == root) ? 1.f : 0.f;
      hd += (float)((cmask >> tok) & 1ull);
    }
    ex *= (1.f / S_);
    pos *= (1.f / 11.2f);
    rp *= (1.f / S_);
    ac *= (1.f / S_);
    hd *= (1.f / S_);
    float ov = (float)__popcll(wm & dmask) * invden;
    regime = hasT ? (0.55f * hd + 0.2f * ov + 0.15f * ac + 0.1f * rp)
                  : (0.45f * ex + 0.3f * ov + 0.1f * ac + 0.15f * rp);
    sims = 0.25f * ex + 0.15f * ov + 0.35f * pos + 0.25f * regime;
    simmax = sims;
    hit = (sims >= 0.6f) ? 1.f : 0.f;
  }
  float sum_sims = bsum(sims, sred);
  float sum_rp   = bsum(rp, sred);
  float sum_reg  = bsum(regime, sred);
  float sum_hit  = bsum(hit, sred);
  float best     = bmax(simmax, sred);

  if (tid == 0) {
    const float invW = 1.f / (float)W_;
    float msims = sum_sims * invW;
    float mrp = sum_rp * invW;
    float mrc = sum_reg * invW;
    float dmass = sum_hit * invW;
    float dcoh = 0.6f * msims + 0.25f * mrp + 0.15f * mrc;
    float pattern_c = 1.f - (0.6f * best + 0.2f * mrp + 0.2f * mrc);
    float contr = 0.2f * hidden_c + 0.2f * token_c + 0.6f * pattern_c;
    contr = fminf(fmaxf(contr, 0.f), 1.f);
    float sh = 0.f;
#pragma unroll
    for (int r = 0; r < RB_; r++) sh += g_shiftp[p][r];
    sh *= (1.f / H_);
    out[0 * NP_ + p] = contr;
    out[1 * NP_ + p] = sh;
    out[2 * NP_ + p] = sim;
    out[3 * NP_ + p] = hidden_c;
    out[4 * NP_ + p] = token_c;
    out[5 * NP_ + p] = pattern_c;
    out[6 * NP_ + p] = dmass;
    out[7 * NP_ + p] = dcoh;
  }
}

extern "C" void kernel_launch(void* const* d_in, const int* in_sizes, int n_in,
                              void* d_out, int out_size) {
  const float* hidden = (const float*)d_in[0];
  const float* anchor = (const float*)d_in[1];
  const int* ids = (const int*)d_in[2];
  const int* ae = (const int*)d_in[3];
  float* out = (float*)d_out;
  dim3 g(NP_, RB_);
  k_all<<<g, 256>>>(hidden, anchor, ids, ae, out);
}

// round 7
// speedup vs baseline: 1.5597x; 1.0187x over previous
#include <cuda_runtime.h>
#include <math.h>

#define B_  8
#define T_  4096
#define D_  1024
#define D4_ 256
#define S_  16
#define H_  256
#define W_  241
#define NP_ 256
#define RB_ 8

// Cross-CTA scratch: per-(pair,rowblock) column partial sums + shift partials.
__device__ float g_partial[NP_][RB_][D_];
__device__ float g_shiftp[NP_][RB_];
__device__ unsigned int g_count[NP_];   // zero-init; finalizer resets -> replay-safe

__constant__ int c_alias[64] = {
  -1,-1,-1,-1,-1,-1,-1,-1,-1,-1,   // 0-9
  -1,11,-1,11,-1,-1,11,-1,-1,-1,   // 10-19
  -1,21,21,21,-1,-1,-1,-1,-1,-1,   // 20-29
  -1,31,31,31,-1,-1,-1,-1,-1,-1,   // 30-39
  -1,41,41,41,41,-1,-1,-1,-1,-1,   // 40-49
  -1,51,51,51,-1,-1,-1,-1,-1,-1,   // 50-59
  -1,-1,-1,-1                      // 60-63
};

__device__ __forceinline__ float bsum(float v, volatile float* sred) {
#pragma unroll
  for (int o = 16; o; o >>= 1) v += __shfl_xor_sync(0xffffffffu, v, o);
  __syncthreads();
  if ((threadIdx.x & 31) == 0) sred[threadIdx.x >> 5] = v;
  __syncthreads();
  float t = 0.f;
#pragma unroll
  for (int i = 0; i < 8; i++) t += sred[i];
  return t;
}
__device__ __forceinline__ float bmax(float v, volatile float* sred) {
#pragma unroll
  for (int o = 16; o; o >>= 1) v = fmaxf(v, __shfl_xor_sync(0xffffffffu, v, o));
  __syncthreads();
  if ((threadIdx.x & 31) == 0) sred[threadIdx.x >> 5] = v;
  __syncthreads();
  float t = sred[0];
#pragma unroll
  for (int i = 1; i < 8; i++) t = fmaxf(t, sred[i]);
  return t;
}

// ---------------------------------------------------------------------------
// Single kernel, grid (256 pairs, 8 rowblocks), 256 threads, occ-5 tuned.
// Each ROW is split between 2 warps (warp parity = column half), so the
// per-thread column accumulator is only 4 float4s -> ~45 regs -> 5 CTAs/SM.
// The 8th CTA to finish a pair runs the finalize inline (fence+atomic).
// ---------------------------------------------------------------------------
__global__ void __launch_bounds__(256, 5) k_all(
    const float* __restrict__ hidden, const float* __restrict__ anchor,
    const int* __restrict__ ids, const int* __restrict__ anchor_end,
    float* __restrict__ out) {
  __shared__ float4 sanchor[D4_];        // 4 KB
  __shared__ float4 swarp[8][128];       // 16 KB
  __shared__ float sHalf[8][8];          // [r][warp] half-row sq-norms
  __shared__ float sred[8];
  __shared__ int ftok[H_];
  __shared__ int sspan[S_];
  __shared__ int salias[64];
  __shared__ int scnt[S_];
  __shared__ int s_last;
  __shared__ int s_root, s_hasT;
  __shared__ float s_invden;
  __shared__ unsigned long long s_dmask, s_cmask;

  const int p = blockIdx.x, rb = blockIdx.y;
  const int tid = threadIdx.x;
  const int warp = tid >> 5, lane = tid & 31;
  const int half = warp & 1;             // column half (0: cols 0-511, 1: 512-1023)
  const int wp = warp >> 1;              // row sub-index within each group of 4
  const int b = p >> 5;
  const int ae = anchor_end[p];
  const int start = ae + 1;

  const float4* anchor4 = (const float4*)(anchor + (size_t)p * D_);
  for (int i = tid; i < D4_; i += 256) sanchor[i] = __ldg(anchor4 + i);
  __syncthreads();

  // ---- Streaming: 32 rows x 1024 cols; warp covers half a row, 8 rows ----
  float4 colacc[4];
#pragma unroll
  for (int j = 0; j < 4; j++) colacc[j] = make_float4(0.f, 0.f, 0.f, 0.f);

  const float4* base4 =
      (const float4*)(hidden + ((size_t)b * T_ + start + rb * 32) * D_) +
      half * 128;
#pragma unroll
  for (int r = 0; r < 8; r++) {
    const float4* row4 = base4 + (size_t)(r * 4 + wp) * D4_;
    float ssq = 0.f;
#pragma unroll
    for (int j = 0; j < 4; j++) {
      float4 x = __ldg(row4 + lane + 32 * j);
      float4 a = sanchor[half * 128 + lane + 32 * j];
      colacc[j].x += x.x; colacc[j].y += x.y;
      colacc[j].z += x.z; colacc[j].w += x.w;
      float d0 = x.x - a.x, d1 = x.y - a.y, d2 = x.z - a.z, d3 = x.w - a.w;
      ssq += d0 * d0 + d1 * d1 + d2 * d2 + d3 * d3;
    }
#pragma unroll
    for (int o = 16; o; o >>= 1) ssq += __shfl_xor_sync(0xffffffffu, ssq, o);
    if (lane == 0) sHalf[r][warp] = ssq;
  }
#pragma unroll
  for (int j = 0; j < 4; j++) swarp[warp][lane + 32 * j] = colacc[j];
  __syncthreads();

  // Row shift: row i = 4*(i>>2)+ (i&3) handled by warps 2*(i&3)+{0,1}
  if (tid < 32) {
    float ssq = sHalf[tid >> 2][(tid & 3) * 2] + sHalf[tid >> 2][(tid & 3) * 2 + 1];
    float v = sqrtf(ssq);
#pragma unroll
    for (int o = 16; o; o >>= 1) v += __shfl_xor_sync(0xffffffffu, v, o);
    if (lane == 0) g_shiftp[p][rb] = v;
  }

  // Column combine: thread tid owns float4 column tid (4 contributing warps)
  {
    const int hh = tid >> 7, cc = tid & 127;
    float4 s = swarp[hh][cc];
#pragma unroll
    for (int w = 1; w < 4; w++) {
      float4 t = swarp[2 * w + hh][cc];
      s.x += t.x; s.y += t.y; s.z += t.z; s.w += t.w;
    }
    ((float4*)g_partial[p][rb])[tid] = s;
  }

  // ---- Arrival protocol: last CTA of the pair finalizes ----
  __threadfence();
  __syncthreads();
  if (tid == 0) {
    unsigned int old = atomicAdd(&g_count[p], 1u);
    s_last = (old == RB_ - 1) ? 1 : 0;
    if (s_last) g_count[p] = 0;   // reset for next graph replay
  }
  __syncthreads();
  if (!s_last) return;
  __threadfence();   // acquire side: order partial reads after the atomic

  // ================== FINALIZE (one CTA per pair) ==================
  ftok[tid] = ids[b * T_ + start + tid];
  if (tid < S_) sspan[tid] = ids[b * T_ + ae - (S_ - 1) + tid];
  if (tid < 64) salias[tid] = c_alias[tid];
  __syncthreads();

  // cosine sim from the 8 rowblock partials (L2-hot)
  float dot, nm, na;
  {
    float4 s = make_float4(0.f, 0.f, 0.f, 0.f);
#pragma unroll
    for (int r = 0; r < RB_; r++) {
      float4 t = ((const float4*)g_partial[p][r])[tid];
      s.x += t.x; s.y += t.y; s.z += t.z; s.w += t.w;
    }
    const float invH = 1.f / H_;
    float4 m = make_float4(s.x * invH, s.y * invH, s.z * invH, s.w * invH);
    float4 a = sanchor[tid];
    dot = m.x * a.x + m.y * a.y + m.z * a.z + m.w * a.w;
    nm  = m.x * m.x + m.y * m.y + m.z * m.z + m.w * m.w;
    na  = a.x * a.x + a.y * a.y + a.z * a.z + a.w * a.w;
  }
  dot = bsum(dot, sred);
  nm = bsum(nm, sred);
  na = bsum(na, sred);
  const float eps = 1e-8f;
  float sim = dot / (fmaxf(sqrtf(na), eps) * fmaxf(sqrtf(nm), eps));
  float hidden_c = fmaxf(0.f, (1.f - sim) * 0.5f);

  int atok = sspan[S_ - 1];
  float tcnt = (ftok[tid] == atok) ? 1.f : 0.f;
  tcnt = bsum(tcnt, sred);
  float token_c = 1.f - tcnt * (1.f / H_);

  // span analysis: counts by 16 threads (no per-thread arrays -> low regs)
  if (tid < S_) {
    int tokv = sspan[tid];
    int c = 0;
    for (int s2 = 0; s2 < S_; s2++) c += (tokv == sspan[s2]);
    scnt[tid] = c;
  }
  __syncthreads();
  if (tid == 0) {
    unsigned long long dm = 0ull;
    for (int s = 0; s < S_; s++) dm |= 1ull << sspan[s];
    int denom = __popcll(dm);
    int maxc = 0;
    for (int s = 0; s < S_; s++) maxc = max(maxc, scnt[s]);
    int mode = 64;
    for (int s = 0; s < S_; s++)
      if (scnt[s] == maxc) mode = min(mode, sspan[s]);
    int root = -1;
    for (int s = 0; s < S_; s++) {
      int al = salias[sspan[s]];
      if (al >= 0) { root = al; break; }
    }
    if (root < 0) root = mode;
    unsigned long long cm = 0ull;
    switch (root) {
      case 11: cm = (1ull<<11)|(1ull<<13)|(1ull<<16); break;
      case 21: cm = (1ull<<14)|(1ull<<15)|(1ull<<21)|(1ull<<22)|(1ull<<23); break;
      case 31: cm = (1ull<<15)|(1ull<<31)|(1ull<<32)|(1ull<<33); break;
      case 41: cm = (1ull<<41)|(1ull<<42)|(1ull<<43)|(1ull<<44); break;
      case 51: cm = (1ull<<15)|(1ull<<51)|(1ull<<52)|(1ull<<53); break;
      default: break;
    }
    s_root = root;
    s_cmask = cm;
    s_hasT = (cm != 0ull) ? 1 : 0;
    s_dmask = dm;
    s_invden = 1.f / (float)denom;
  }
  __syncthreads();

  const int root = s_root;
  const unsigned long long cmask = s_cmask, dmask = s_dmask;
  const int hasT = s_hasT;
  const float invden = s_invden;

  float sims = 0.f, rp = 0.f, regime = 0.f, hit = 0.f;
  float simmax = -1e30f;
  if (tid < W_) {
    float ex = 0.f, pos = 0.f, ac = 0.f, hd = 0.f;
    unsigned long long wm = 0ull;
#pragma unroll
    for (int s = 0; s < S_; s++) {
      int tok = ftok[tid + s];
      wm |= 1ull << tok;
      float eq = (tok == sspan[s]) ? 1.f : 0.f;
      ex += eq;
      pos += eq * (1.0f - 0.04f * (float)s);
      rp += (tok == root) ? 1.f : 0.f;
      ac += (salias[tok] == root) ? 1.f : 0.f;
      hd += (float)((cmask >> tok) & 1ull);
    }
    ex *= (1.f / S_);
    pos *= (1.f / 11.2f);
    rp *= (1.f / S_);
    ac *= (1.f / S_);
    hd *= (1.f / S_);
    float ov = (float)__popcll(wm & dmask) * invden;
    regime = hasT ? (0.55f * hd + 0.2f * ov + 0.15f * ac + 0.1f * rp)
                  : (0.45f * ex + 0.3f * ov + 0.1f * ac + 0.15f * rp);
    sims = 0.25f * ex + 0.15f * ov + 0.35f * pos + 0.25f * regime;
    simmax = sims;
    hit = (sims >= 0.6f) ? 1.f : 0.f;
  }
  float sum_sims = bsum(sims, sred);
  float sum_rp   = bsum(rp, sred);
  float sum_reg  = bsum(regime, sred);
  float sum_hit  = bsum(hit, sred);
  float best     = bmax(simmax, sred);

  if (tid == 0) {
    const float invW = 1.f / (float)W_;
    float msims = sum_sims * invW;
    float mrp = sum_rp * invW;
    float mrc = sum_reg * invW;
    float dmass = sum_hit * invW;
    float dcoh = 0.6f * msims + 0.25f * mrp + 0.15f * mrc;
    float pattern_c = 1.f - (0.6f * best + 0.2f * mrp + 0.2f * mrc);
    float contr = 0.2f * hidden_c + 0.2f * token_c + 0.6f * pattern_c;
    contr = fminf(fmaxf(contr, 0.f), 1.f);
    float sh = 0.f;
#pragma unroll
    for (int r = 0; r < RB_; r++) sh += g_shiftp[p][r];
    sh *= (1.f / H_);
    out[0 * NP_ + p] = contr;
    out[1 * NP_ + p] = sh;
    out[2 * NP_ + p] = sim;
    out[3 * NP_ + p] = hidden_c;
    out[4 * NP_ + p] = token_c;
    out[5 * NP_ + p] = pattern_c;
    out[6 * NP_ + p] = dmass;
    out[7 * NP_ + p] = dcoh;
  }
}

extern "C" void kernel_launch(void* const* d_in, const int* in_sizes, int n_in,
                              void* d_out, int out_size) {
  const float* hidden = (const float*)d_in[0];
  const float* anchor = (const float*)d_in[1];
  const int* ids = (const int*)d_in[2];
  const int* ae = (const int*)d_in[3];
  float* out = (float*)d_out;
  dim3 g(NP_, RB_);
  k_all<<<g, 256>>>(hidden, anchor, ids, ae, out);
}

// round 10
// speedup vs baseline: 1.5673x; 1.0049x over previous
#include <cuda_runtime.h>
#include <math.h>

#define B_  8
#define T_  4096
#define D_  1024
#define D4_ 256
#define S_  16
#define H_  256
#define W_  241
#define NP_ 256
#define RB_ 8

// Cross-CTA scratch: per-(pair,rowblock) column partial sums + shift partials.
__device__ float g_partial[NP_][RB_][D_];
__device__ float g_shiftp[NP_][RB_];
__device__ unsigned int g_count[NP_];   // zero-init; finalizer resets -> replay-safe

__constant__ int c_alias[64] = {
  -1,-1,-1,-1,-1,-1,-1,-1,-1,-1,   // 0-9
  -1,11,-1,11,-1,-1,11,-1,-1,-1,   // 10-19
  -1,21,21,21,-1,-1,-1,-1,-1,-1,   // 20-29
  -1,31,31,31,-1,-1,-1,-1,-1,-1,   // 30-39
  -1,41,41,41,41,-1,-1,-1,-1,-1,   // 40-49
  -1,51,51,51,-1,-1,-1,-1,-1,-1,   // 50-59
  -1,-1,-1,-1                      // 60-63
};

__device__ __forceinline__ float bsum(float v, volatile float* sred) {
#pragma unroll
  for (int o = 16; o; o >>= 1) v += __shfl_xor_sync(0xffffffffu, v, o);
  __syncthreads();
  if ((threadIdx.x & 31) == 0) sred[threadIdx.x >> 5] = v;
  __syncthreads();
  float t = 0.f;
#pragma unroll
  for (int i = 0; i < 8; i++) t += sred[i];
  return t;
}
__device__ __forceinline__ float bmax(float v, volatile float* sred) {
#pragma unroll
  for (int o = 16; o; o >>= 1) v = fmaxf(v, __shfl_xor_sync(0xffffffffu, v, o));
  __syncthreads();
  if ((threadIdx.x & 31) == 0) sred[threadIdx.x >> 5] = v;
  __syncthreads();
  float t = sred[0];
#pragma unroll
  for (int i = 1; i < 8; i++) t = fmaxf(t, sred[i]);
  return t;
}

// ---------------------------------------------------------------------------
// Single kernel, grid (256 pairs, 8 rowblocks), 256 threads.
// Half-row warps (warp parity = column half); explicit 2-stage software
// pipeline in the stream loop so >=4 LDG.128 stay in flight per warp.
// No shuffles in the hot loop: lane-local sq-norm partials go to smem.
// The 8th CTA to finish a pair runs the finalize inline (fence+atomic).
// ---------------------------------------------------------------------------
__global__ void __launch_bounds__(256, 4) k_all(
    const float* __restrict__ hidden, const float* __restrict__ anchor,
    const int* __restrict__ ids, const int* __restrict__ anchor_end,
    float* __restrict__ out) {
  __shared__ float4 sanchor[D4_];        // 4 KB
  __shared__ float4 swarp[8][128];       // 16 KB
  __shared__ float sSsq[8][8][33];       // 8.25 KB  [warp][r][lane] padded
  __shared__ float sred[8];
  __shared__ int ftok[H_];
  __shared__ int sspan[S_];
  __shared__ int salias[64];
  __shared__ int scnt[S_];
  __shared__ int s_last;
  __shared__ int s_root, s_hasT;
  __shared__ float s_invden;
  __shared__ unsigned long long s_dmask, s_cmask;

  const int p = blockIdx.x, rb = blockIdx.y;
  const int tid = threadIdx.x;
  const int warp = tid >> 5, lane = tid & 31;
  const int half = warp & 1;             // column half (0: cols 0-511, 1: 512-1023)
  const int wp = warp >> 1;              // row sub-index within each group of 4
  const int b = p >> 5;
  const int ae = anchor_end[p];
  const int start = ae + 1;

  const float4* anchor4 = (const float4*)(anchor + (size_t)p * D_);
  for (int i = tid; i < D4_; i += 256) sanchor[i] = __ldg(anchor4 + i);
  __syncthreads();

  // ---- Streaming: 32 rows x 1024 cols; warp covers half of row 4r+wp ----
  float4 colacc[4];
#pragma unroll
  for (int j = 0; j < 4; j++) colacc[j] = make_float4(0.f, 0.f, 0.f, 0.f);

  const float4* base4 =
      (const float4*)(hidden + ((size_t)b * T_ + start + rb * 32) * D_) +
      half * 128 + (size_t)wp * D4_;

  // Prologue: batch-load r=0
  float4 x0 = __ldg(base4 + lane);
  float4 x1 = __ldg(base4 + lane + 32);
  float4 x2 = __ldg(base4 + lane + 64);
  float4 x3 = __ldg(base4 + lane + 96);

#pragma unroll
  for (int r = 0; r < 8; r++) {
    float4 n0, n1, n2, n3;
    if (r < 7) {   // prefetch next row's batch BEFORE consuming current
      const float4* np = base4 + (size_t)(r + 1) * 4 * D4_;
      n0 = __ldg(np + lane);
      n1 = __ldg(np + lane + 32);
      n2 = __ldg(np + lane + 64);
      n3 = __ldg(np + lane + 96);
    }
    // consume current batch; anchors from smem (keeps regs for the pipeline)
    float ssq = 0.f;
    {
      float4 a = sanchor[half * 128 + lane];
      colacc[0].x += x0.x; colacc[0].y += x0.y; colacc[0].z += x0.z; colacc[0].w += x0.w;
      float d0 = x0.x - a.x, d1 = x0.y - a.y, d2 = x0.z - a.z, d3 = x0.w - a.w;
      ssq += d0 * d0 + d1 * d1 + d2 * d2 + d3 * d3;
    }
    {
      float4 a = sanchor[half * 128 + lane + 32];
      colacc[1].x += x1.x; colacc[1].y += x1.y; colacc[1].z += x1.z; colacc[1].w += x1.w;
      float d0 = x1.x - a.x, d1 = x1.y - a.y, d2 = x1.z - a.z, d3 = x1.w - a.w;
      ssq += d0 * d0 + d1 * d1 + d2 * d2 + d3 * d3;
    }
    {
      float4 a = sanchor[half * 128 + lane + 64];
      colacc[2].x += x2.x; colacc[2].y += x2.y; colacc[2].z += x2.z; colacc[2].w += x2.w;
      float d0 = x2.x - a.x, d1 = x2.y - a.y, d2 = x2.z - a.z, d3 = x2.w - a.w;
      ssq += d0 * d0 + d1 * d1 + d2 * d2 + d3 * d3;
    }
    {
      float4 a = sanchor[half * 128 + lane + 96];
      colacc[3].x += x3.x; colacc[3].y += x3.y; colacc[3].z += x3.z; colacc[3].w += x3.w;
      float d0 = x3.x - a.x, d1 = x3.y - a.y, d2 = x3.z - a.z, d3 = x3.w - a.w;
      ssq += d0 * d0 + d1 * d1 + d2 * d2 + d3 * d3;
    }
    sSsq[warp][r][lane] = ssq;   // lane-local; no shuffle in hot loop
    if (r < 7) { x0 = n0; x1 = n1; x2 = n2; x3 = n3; }
  }
#pragma unroll
  for (int j = 0; j < 4; j++) swarp[warp][lane + 32 * j] = colacc[j];
  __syncthreads();

  // Row shift: thread t (<32) owns row t = 4*(t>>2)+(t&3); sums both halves.
  if (tid < 32) {
    const int r = tid >> 2, w0 = (tid & 3) * 2;
    float s = 0.f;
#pragma unroll 8
    for (int l = 0; l < 32; l++) s += sSsq[w0][r][l] + sSsq[w0 + 1][r][l];
    float v = sqrtf(s);
#pragma unroll
    for (int o = 16; o; o >>= 1) v += __shfl_xor_sync(0xffffffffu, v, o);
    if (lane == 0) g_shiftp[p][rb] = v;
  }

  // Column combine: thread tid owns float4 column tid (4 contributing warps)
  {
    const int hh = tid >> 7, cc = tid & 127;
    float4 s = swarp[hh][cc];
#pragma unroll
    for (int w = 1; w < 4; w++) {
      float4 t = swarp[2 * w + hh][cc];
      s.x += t.x; s.y += t.y; s.z += t.z; s.w += t.w;
    }
    ((float4*)g_partial[p][rb])[tid] = s;
  }

  // ---- Arrival protocol: last CTA of the pair finalizes ----
  __threadfence();
  __syncthreads();
  if (tid == 0) {
    unsigned int old = atomicAdd(&g_count[p], 1u);
    s_last = (old == RB_ - 1) ? 1 : 0;
    if (s_last) g_count[p] = 0;   // reset for next graph replay
  }
  __syncthreads();
  if (!s_last) return;
  __threadfence();   // acquire side: order partial reads after the atomic

  // ================== FINALIZE (one CTA per pair) ==================
  ftok[tid] = ids[b * T_ + start + tid];
  if (tid < S_) sspan[tid] = ids[b * T_ + ae - (S_ - 1) + tid];
  if (tid < 64) salias[tid] = c_alias[tid];
  __syncthreads();

  // cosine sim from the 8 rowblock partials (L2-hot)
  float dot, nm, na;
  {
    float4 s = make_float4(0.f, 0.f, 0.f, 0.f);
#pragma unroll
    for (int r = 0; r < RB_; r++) {
      float4 t = ((const float4*)g_partial[p][r])[tid];
      s.x += t.x; s.y += t.y; s.z += t.z; s.w += t.w;
    }
    const float invH = 1.f / H_;
    float4 m = make_float4(s.x * invH, s.y * invH, s.z * invH, s.w * invH);
    float4 a = sanchor[tid];
    dot = m.x * a.x + m.y * a.y + m.z * a.z + m.w * a.w;
    nm  = m.x * m.x + m.y * m.y + m.z * m.z + m.w * m.w;
    na  = a.x * a.x + a.y * a.y + a.z * a.z + a.w * a.w;
  }
  dot = bsum(dot, sred);
  nm = bsum(nm, sred);
  na = bsum(na, sred);
  const float eps = 1e-8f;
  float sim = dot / (fmaxf(sqrtf(na), eps) * fmaxf(sqrtf(nm), eps));
  float hidden_c = fmaxf(0.f, (1.f - sim) * 0.5f);

  int atok = sspan[S_ - 1];
  float tcnt = (ftok[tid] == atok) ? 1.f : 0.f;
  tcnt = bsum(tcnt, sred);
  float token_c = 1.f - tcnt * (1.f / H_);

  // span analysis: counts by 16 threads (no per-thread arrays -> low regs)
  if (tid < S_) {
    int tokv = sspan[tid];
    int c = 0;
    for (int s2 = 0; s2 < S_; s2++) c += (tokv == sspan[s2]);
    scnt[tid] = c;
  }
  __syncthreads();
  if (tid == 0) {
    unsigned long long dm = 0ull;
    for (int s = 0; s < S_; s++) dm |= 1ull << sspan[s];
    int denom = __popcll(dm);
    int maxc = 0;
    for (int s = 0; s < S_; s++) maxc = max(maxc, scnt[s]);
    int mode = 64;
    for (int s = 0; s < S_; s++)
      if (scnt[s] == maxc) mode = min(mode, sspan[s]);
    int root = -1;
    for (int s = 0; s < S_; s++) {
      int al = salias[sspan[s]];
      if (al >= 0) { root = al; break; }
    }
    if (root < 0) root = mode;
    unsigned long long cm = 0ull;
    switch (root) {
      case 11: cm = (1ull<<11)|(1ull<<13)|(1ull<<16); break;
      case 21: cm = (1ull<<14)|(1ull<<15)|(1ull<<21)|(1ull<<22)|(1ull<<23); break;
      case 31: cm = (1ull<<15)|(1ull<<31)|(1ull<<32)|(1ull<<33); break;
      case 41: cm = (1ull<<41)|(1ull<<42)|(1ull<<43)|(1ull<<44); break;
      case 51: cm = (1ull<<15)|(1ull<<51)|(1ull<<52)|(1ull<<53); break;
      default: break;
    }
    s_root = root;
    s_cmask = cm;
    s_hasT = (cm != 0ull) ? 1 : 0;
    s_dmask = dm;
    s_invden = 1.f / (float)denom;
  }
  __syncthreads();

  const int root = s_root;
  const unsigned long long cmask = s_cmask, dmask = s_dmask;
  const int hasT = s_hasT;
  const float invden = s_invden;

  float sims = 0.f, rp = 0.f, regime = 0.f, hit = 0.f;
  float simmax = -1e30f;
  if (tid < W_) {
    float ex = 0.f, pos = 0.f, ac = 0.f, hd = 0.f;
    unsigned long long wm = 0ull;
#pragma unroll
    for (int s = 0; s < S_; s++) {
      int tok = ftok[tid + s];
      wm |= 1ull << tok;
      float eq = (tok == sspan[s]) ? 1.f : 0.f;
      ex += eq;
      pos += eq * (1.0f - 0.04f * (float)s);
      rp += (tok == root) ? 1.f : 0.f;
      ac += (salias[tok] == root) ? 1.f : 0.f;
      hd += (float)((cmask >> tok) & 1ull);
    }
    ex *= (1.f / S_);
    pos *= (1.f / 11.2f);
    rp *= (1.f / S_);
    ac *= (1.f / S_);
    hd *= (1.f / S_);
    float ov = (float)__popcll(wm & dmask) * invden;
    regime = hasT ? (0.55f * hd + 0.2f * ov + 0.15f * ac + 0.1f * rp)
                  : (0.45f * ex + 0.3f * ov + 0.1f * ac + 0.15f * rp);
    sims = 0.25f * ex + 0.15f * ov + 0.35f * pos + 0.25f * regime;
    simmax = sims;
    hit = (sims >= 0.6f) ? 1.f : 0.f;
  }
  float sum_sims = bsum(sims, sred);
  float sum_rp   = bsum(rp, sred);
  float sum_reg  = bsum(regime, sred);
  float sum_hit  = bsum(hit, sred);
  float best     = bmax(simmax, sred);

  if (tid == 0) {
    const float invW = 1.f / (float)W_;
    float msims = sum_sims * invW;
    float mrp = sum_rp * invW;
    float mrc = sum_reg * invW;
    float dmass = sum_hit * invW;
    float dcoh = 0.6f * msims + 0.25f * mrp + 0.15f * mrc;
    float pattern_c = 1.f - (0.6f * best + 0.2f * mrp + 0.2f * mrc);
    float contr = 0.2f * hidden_c + 0.2f * token_c + 0.6f * pattern_c;
    contr = fminf(fmaxf(contr, 0.f), 1.f);
    float sh = 0.f;
#pragma unroll
    for (int r = 0; r < RB_; r++) sh += g_shiftp[p][r];
    sh *= (1.f / H_);
    out[0 * NP_ + p] = contr;
    out[1 * NP_ + p] = sh;
    out[2 * NP_ + p] = sim;
    out[3 * NP_ + p] = hidden_c;
    out[4 * NP_ + p] = token_c;
    out[5 * NP_ + p] = pattern_c;
    out[6 * NP_ + p] = dmass;
    out[7 * NP_ + p] = dcoh;
  }
}

extern "C" void kernel_launch(void* const* d_in, const int* in_sizes, int n_in,
                              void* d_out, int out_size) {
  const float* hidden = (const float*)d_in[0];
  const float* anchor = (const float*)d_in[1];
  const int* ids = (const int*)d_in[2];
  const int* ae = (const int*)d_in[3];
  float* out = (float*)d_out;
  dim3 g(NP_, RB_);
  k_all<<<g, 256>>>(hidden, anchor, ids, ae, out);
}